// round 16
// baseline (speedup 1.0000x reference)
#include <cuda_runtime.h>
#include <math.h>
#include <stdint.h>

#define HEADS 12
#define DIM   64
#define BATCH 2
#define SEQ   2048
#define EMB   768
#define QKVN  (3 * HEADS * DIM)   // 2304
#define ROWS  (BATCH * SEQ)       // 4096
#define MASKN (BATCH * SEQ * SEQ) // 8388608

// ----- device scratch (all tf32-as-uint32) -----
__device__ uint32_t g_qtf[ROWS * EMB];     // Q, d-cols permuted per 8-block
__device__ uint32_t g_ktf[ROWS * EMB];     // K, d-cols permuted per 8-block
__device__ uint32_t g_vtf[ROWS * EMB];     // V transposed: [b][h][d][token]
__device__ uint32_t g_xtf[ROWS * EMB];
__device__ uint32_t g_atttf[ROWS * EMB];
__device__ uint32_t g_wpretf[EMB * QKVN];
__device__ uint32_t g_wprojtf[EMB * EMB];
__device__ int   g_mask_esize;
__device__ int   g_mask_allones;

// ============================ helpers =======================================
__device__ __forceinline__ uint32_t to_tf32(float x) {
    uint32_t r;
    asm("cvt.rna.tf32.f32 %0, %1;" : "=r"(r) : "f"(x));
    return r;
}
__device__ __forceinline__ void mma_tf32(float c[4],
                                         uint32_t a0, uint32_t a1, uint32_t a2, uint32_t a3,
                                         uint32_t b0, uint32_t b1) {
    asm volatile(
        "mma.sync.aligned.m16n8k8.row.col.f32.tf32.tf32.f32 "
        "{%0,%1,%2,%3}, {%4,%5,%6,%7}, {%8,%9}, {%0,%1,%2,%3};"
        : "+f"(c[0]), "+f"(c[1]), "+f"(c[2]), "+f"(c[3])
        : "r"(a0), "r"(a1), "r"(a2), "r"(a3), "r"(b0), "r"(b1));
}
#define CP16(dst, src) \
    asm volatile("cp.async.cg.shared.global [%0], [%1], 16;" :: "r"(dst), "l"(src) : "memory")
#define CP_COMMIT() asm volatile("cp.async.commit_group;" ::: "memory")
#define CP_WAIT1() asm volatile("cp.async.wait_group 1;" ::: "memory")
#define CP_WAIT0() asm volatile("cp.async.wait_group 0;" ::: "memory")

// perm within 8-block: 0,4,1,5,2,6,3,7 -> positions (b<4 ? 2b : 2(b-4)+1)
__device__ __forceinline__ int perm8(int b) { return (b < 4) ? 2 * b : 2 * (b - 4) + 1; }

// ============================ fused prepass: fp32 -> tf32 ===================
#define XN4  (ROWS * EMB / 4)
#define WPN4 (EMB * QKVN / 4)
#define WJN4 (EMB * EMB / 4)
#define TOTN4 (XN4 + WPN4 + WJN4)

__global__ void cvt_all_kernel(const float4* __restrict__ x,
                               const float4* __restrict__ wpre,
                               const float4* __restrict__ wproj,
                               uint4* __restrict__ xo,
                               uint4* __restrict__ wpo,
                               uint4* __restrict__ wjo) {
    for (int i = blockIdx.x * blockDim.x + threadIdx.x; i < TOTN4;
         i += gridDim.x * blockDim.x) {
        const float4* src;
        uint4* dst;
        int k;
        if (i < XN4) { src = x; dst = xo; k = i; }
        else if (i < XN4 + WPN4) { src = wpre; dst = wpo; k = i - XN4; }
        else { src = wproj; dst = wjo; k = i - XN4 - WPN4; }
        float4 v = src[k];
        dst[k] = make_uint4(to_tf32(v.x), to_tf32(v.y), to_tf32(v.z), to_tf32(v.w));
    }
}

// ============================ GEMM 128x128 tile (single tf32) ===============
#define G5_BYTES 71680

template <int MODE>
__global__ void __launch_bounds__(256, 2)
gemm_tf_kernel(const uint32_t* __restrict__ Atf, const uint32_t* __restrict__ Btf,
               const float* __restrict__ bias, float* __restrict__ C,
               uint32_t* __restrict__ qtf, uint32_t* __restrict__ ktf,
               uint32_t* __restrict__ vtf,
               int M, int N, int K) {
    extern __shared__ char smraw[];
    uint32_t* usm = reinterpret_cast<uint32_t*>(smraw);
    const uint32_t sb = (uint32_t)__cvta_generic_to_shared(smraw);

    const int tid = threadIdx.x;
    const int wid = tid >> 5;
    const int lane = tid & 31;
    const int g  = lane >> 2;
    const int tq = lane & 3;
    const int wm = wid >> 1;
    const int wn = wid & 1;
    const int m0 = blockIdx.y * 128;
    const int n0 = blockIdx.x * 128;
    const int nkt = K / 32;

    float acc[2][8][4];
#pragma unroll
    for (int i = 0; i < 2; i++)
#pragma unroll
        for (int j = 0; j < 8; j++)
#pragma unroll
            for (int r = 0; r < 4; r++) acc[i][j][r] = 0.0f;

    auto issue_tile = [&](int s, int kt) {
#pragma unroll
        for (int p = 0; p < 4; p++) {
            int idx = p * 256 + tid;
            int r = idx >> 3, ch = idx & 7;
            const uint32_t* src = Atf + (size_t)(m0 + r) * K + kt * 32 + ch * 4;
            uint32_t dst = sb + s * 18432 + (r * 36 + ch * 4) * 4;
            CP16(dst, src);
        }
#pragma unroll
        for (int p = 0; p < 4; p++) {
            int idx = p * 256 + tid;
            int r = idx >> 5, ch = idx & 31;
            const uint32_t* src = Btf + (size_t)(kt * 32 + r) * N + n0 + ch * 4;
            uint32_t dst = sb + 36864 + s * 17408 + (r * 136 + ch * 4) * 4;
            CP16(dst, src);
        }
        CP_COMMIT();
    };

    issue_tile(0, 0);

    for (int kt = 0; kt < nkt; kt++) {
        const int s = kt & 1;
        if (kt + 1 < nkt) {
            issue_tile(1 - s, kt + 1);
            CP_WAIT1();
        } else {
            CP_WAIT0();
        }
        __syncthreads();

        const uint32_t* sA = usm + s * 4608;
        const uint32_t* sB = usm + 9216 + s * 4352;

#pragma unroll
        for (int ks = 0; ks < 4; ks++) {
            const int kb = ks * 8;
            uint32_t af[2][4];
#pragma unroll
            for (int i = 0; i < 2; i++) {
                const int rbase = (wm * 32 + i * 16 + g) * 36 + kb + tq;
                af[i][0] = sA[rbase];
                af[i][1] = sA[rbase + 8 * 36];
                af[i][2] = sA[rbase + 4];
                af[i][3] = sA[rbase + 8 * 36 + 4];
            }
            uint32_t bf[8][2];
#pragma unroll
            for (int j = 0; j < 8; j++) {
                const int col = wn * 64 + j * 8 + g;
                bf[j][0] = sB[(kb + tq) * 136 + col];
                bf[j][1] = sB[(kb + tq + 4) * 136 + col];
            }
#pragma unroll
            for (int i = 0; i < 2; i++)
#pragma unroll
                for (int j = 0; j < 8; j++)
                    mma_tf32(acc[i][j], af[i][0], af[i][1], af[i][2], af[i][3],
                             bf[j][0], bf[j][1]);
        }
        __syncthreads();
    }

    const int region = n0 / EMB;
#pragma unroll
    for (int i = 0; i < 2; i++) {
        const int row = m0 + wm * 32 + i * 16 + g;
#pragma unroll
        for (int j = 0; j < 8; j++) {
            const int col = n0 + wn * 64 + j * 8 + 2 * tq;
            const float b0 = bias[col], b1 = bias[col + 1];
            float v00 = acc[i][j][0] + b0, v01 = acc[i][j][1] + b1;
            float v10 = acc[i][j][2] + b0, v11 = acc[i][j][3] + b1;
            if (MODE == 0) {
                *reinterpret_cast<float2*>(&C[(size_t)row * N + col]) =
                    make_float2(v00, v01);
                *reinterpret_cast<float2*>(&C[(size_t)(row + 8) * N + col]) =
                    make_float2(v10, v11);
            } else {
                const int cemb = col - region * EMB;
                if (region == 2) {
                    // V transposed: [b][h][d][token]
                    const int hh = cemb >> 6, d = cemb & 63;
                    const size_t vb0 = ((size_t)((row >> 11) * HEADS + hh) * 64);
                    const size_t vb1 = ((size_t)(((row + 8) >> 11) * HEADS + hh) * 64);
                    const int t0 = row & 2047, t1 = (row + 8) & 2047;
                    vtf[(vb0 + d) * SEQ + t0]     = to_tf32(v00);
                    vtf[(vb0 + d + 1) * SEQ + t0] = to_tf32(v01);
                    vtf[(vb1 + d) * SEQ + t1]     = to_tf32(v10);
                    vtf[(vb1 + d + 1) * SEQ + t1] = to_tf32(v11);
                } else {
                    // Q/K: permuted d-columns within 8-block
                    uint32_t* dst = (region == 0) ? qtf : ktf;
                    const float sc = (region == 0) ? 0.125f : 1.0f;
                    const int bb = 2 * tq;
                    const int base = cemb - bb;
                    const int pe = perm8(bb), po = perm8(bb + 1);
                    dst[(size_t)row * EMB + base + pe] = to_tf32(sc * v00);
                    dst[(size_t)row * EMB + base + po] = to_tf32(sc * v01);
                    dst[(size_t)(row + 8) * EMB + base + pe] = to_tf32(sc * v10);
                    dst[(size_t)(row + 8) * EMB + base + po] = to_tf32(sc * v11);
                }
            }
        }
    }
}

// ============================ mask scan (detect fused) ======================
__device__ __forceinline__ unsigned int haszero_byte(unsigned int v) {
    return (v - 0x01010101u) & ~v & 0x80808080u;
}

__global__ void mask_scan_kernel(const uint4* __restrict__ mask) {
    unsigned int w0 = ((const unsigned int*)mask)[0];
    int esize;
    if (w0 == 0x01010101u) esize = 1;
    else if (w0 == 1u || w0 == 0x3f800000u) esize = 4;
    else if ((w0 & 0xFFu) != 0u || (w0 >> 8) == 0u) esize = 1;
    else esize = 4;
    if (blockIdx.x == 0 && threadIdx.x == 0) {
        g_mask_esize = esize;
        g_mask_allones = 1;
    }
    unsigned int any = 0;
    if (esize == 4) {
        const int n = MASKN / 4;
        for (int i = blockIdx.x * blockDim.x + threadIdx.x; i < n;
             i += gridDim.x * blockDim.x) {
            uint4 w = mask[i];
            any |= (w.x == 0u) | (w.y == 0u) | (w.z == 0u) | (w.w == 0u);
        }
    } else {
        const int n = MASKN / 16;
        for (int i = blockIdx.x * blockDim.x + threadIdx.x; i < n;
             i += gridDim.x * blockDim.x) {
            uint4 w = mask[i];
            any |= haszero_byte(w.x) | haszero_byte(w.y) |
                   haszero_byte(w.z) | haszero_byte(w.w);
        }
    }
    if (any) g_mask_allones = 0;
}

// ============================ attention (LDS64 everywhere) ==================
// 256 threads (8 warps), 128 q-rows, 64-key chunks, double-buffered cp.async.
// Q/K d-permuted in gmem; V transposed [b][h][d][token]. All frag pair-loads
// are LDS64, stride 72 (conflict-free for 16-lane 8B transactions).
// smem fl: stage s: K @ s*9216 [64][72]; Vt @ s*9216+4608 [64][72].
// Q staged in stage-1 region (128x72 = 9216 fl exactly).
#define AT4_BYTES (18432 * 4)

__global__ void __launch_bounds__(256, 2)
attn_mma_kernel(const uint32_t* __restrict__ qtf, const uint32_t* __restrict__ ktf,
                const uint32_t* __restrict__ vtf,
                const void* __restrict__ mask,
                uint32_t* __restrict__ atttf) {
    extern __shared__ float sh[];
    const uint32_t sb = (uint32_t)__cvta_generic_to_shared(sh);

    const int tid = threadIdx.x;
    const int wid = tid >> 5;
    const int lane = tid & 31;
    const int g  = lane >> 2;
    const int tq = lane & 3;
    const int wq = wid * 16;
    const int q0 = blockIdx.x * 128;
    const int h  = blockIdx.y;
    const int b  = blockIdx.z;

    const int mask_allones = g_mask_allones;
    const int mask_esize   = g_mask_esize;
    const size_t rbase = (size_t)b * SEQ;
    const int hoff = h * DIM;
    const size_t mask_base = (size_t)b * SEQ * SEQ;
    const size_t vhead = ((size_t)(b * HEADS + h)) * 64;   // V^T row base (d rows)

    auto issue_kv = [&](int s, int kt) {
        const int k0 = kt * 64;
#pragma unroll
        for (int p = 0; p < 4; p++) {          // K: 64 key-rows x 16 chunks
            int idx = p * 256 + tid;
            int key = idx >> 4, c = idx & 15;
            const uint32_t* src = ktf + (rbase + k0 + key) * EMB + hoff + c * 4;
            uint32_t dst = sb + (s * 9216 + key * 72 + c * 4) * 4;
            CP16(dst, src);
        }
#pragma unroll
        for (int p = 0; p < 4; p++) {          // V^T: 64 d-rows x 16 chunks
            int idx = p * 256 + tid;
            int d = idx >> 4, c = idx & 15;
            const uint32_t* src = vtf + (vhead + d) * SEQ + k0 + c * 4;
            uint32_t dst = sb + (s * 9216 + 4608 + d * 72 + c * 4) * 4;
            CP16(dst, src);
        }
        CP_COMMIT();
    };

    // ---- stage Q (permuted layout) into stage-1 region ----
#pragma unroll
    for (int p = 0; p < 8; p++) {
        int idx = p * 256 + tid;
        int r = idx >> 4, c = idx & 15;
        const uint32_t* src = qtf + (rbase + q0 + r) * EMB + hoff + c * 4;
        uint32_t dst = sb + (9216 + r * 72 + c * 4) * 4;
        CP16(dst, src);
    }
    CP_COMMIT();
    CP_WAIT0();
    __syncthreads();

    const uint32_t* Qstage = reinterpret_cast<const uint32_t*>(sh + 9216);
    uint32_t qf[8][4];
#pragma unroll
    for (int kb = 0; kb < 8; kb++) {
        uint2 p0 = *reinterpret_cast<const uint2*>(
            &Qstage[(wq + g) * 72 + kb * 8 + 2 * tq]);
        uint2 p1 = *reinterpret_cast<const uint2*>(
            &Qstage[(wq + g + 8) * 72 + kb * 8 + 2 * tq]);
        qf[kb][0] = p0.x; qf[kb][2] = p0.y;
        qf[kb][1] = p1.x; qf[kb][3] = p1.y;
    }
    __syncthreads();
    issue_kv(0, 0);

    float o[8][4];
#pragma unroll
    for (int nt = 0; nt < 8; nt++)
#pragma unroll
        for (int r = 0; r < 4; r++) o[nt][r] = 0.0f;
    float m0r = -1e30f, m1r = -1e30f, l0r = 0.0f, l1r = 0.0f;

    const int nkt = SEQ / 64;
    for (int kt = 0; kt < nkt; kt++) {
        const int s = kt & 1;
        const int k0 = kt * 64;
        if (kt + 1 < nkt) {
            issue_kv(1 - s, kt + 1);
            CP_WAIT1();
        } else {
            CP_WAIT0();
        }
        __syncthreads();

        const uint32_t* Ktf_s = reinterpret_cast<const uint32_t*>(sh + s * 9216);
        const uint32_t* Vt_s = reinterpret_cast<const uint32_t*>(sh + s * 9216 + 4608);

        // ---- S = (Q/8) K^T  (LDS64 b-frags) ----
        float s4[8][4];
#pragma unroll
        for (int nt = 0; nt < 8; nt++)
#pragma unroll
            for (int r = 0; r < 4; r++) s4[nt][r] = 0.0f;
#pragma unroll
        for (int kb = 0; kb < 8; kb++) {
            const int koff = kb * 8 + 2 * tq;
#pragma unroll
            for (int nt = 0; nt < 8; nt++) {
                uint2 kk = *reinterpret_cast<const uint2*>(
                    &Ktf_s[(nt * 8 + g) * 72 + koff]);
                mma_tf32(s4[nt], qf[kb][0], qf[kb][1], qf[kb][2], qf[kb][3],
                         kk.x, kk.y);
            }
        }

        // ---- mask ----
        if (!mask_allones) {
            const int qg0 = q0 + wq + g, qg1 = qg0 + 8;
#pragma unroll
            for (int nt = 0; nt < 8; nt++) {
                int kcol = k0 + nt * 8 + 2 * tq;
                bool mk[4];
                if (mask_esize == 4) {
                    const unsigned int* mm = (const unsigned int*)mask;
                    mk[0] = mm[mask_base + (size_t)qg0 * SEQ + kcol] != 0;
                    mk[1] = mm[mask_base + (size_t)qg0 * SEQ + kcol + 1] != 0;
                    mk[2] = mm[mask_base + (size_t)qg1 * SEQ + kcol] != 0;
                    mk[3] = mm[mask_base + (size_t)qg1 * SEQ + kcol + 1] != 0;
                } else {
                    const unsigned char* mm = (const unsigned char*)mask;
                    mk[0] = mm[mask_base + (size_t)qg0 * SEQ + kcol] != 0;
                    mk[1] = mm[mask_base + (size_t)qg0 * SEQ + kcol + 1] != 0;
                    mk[2] = mm[mask_base + (size_t)qg1 * SEQ + kcol] != 0;
                    mk[3] = mm[mask_base + (size_t)qg1 * SEQ + kcol + 1] != 0;
                }
#pragma unroll
                for (int r = 0; r < 4; r++)
                    if (!mk[r]) s4[nt][r] = -1e9f;
            }
        }

        // ---- online softmax ----
        float mt0 = -1e30f, mt1 = -1e30f;
#pragma unroll
        for (int nt = 0; nt < 8; nt++) {
            mt0 = fmaxf(mt0, fmaxf(s4[nt][0], s4[nt][1]));
            mt1 = fmaxf(mt1, fmaxf(s4[nt][2], s4[nt][3]));
        }
        mt0 = fmaxf(mt0, __shfl_xor_sync(0xffffffff, mt0, 1));
        mt0 = fmaxf(mt0, __shfl_xor_sync(0xffffffff, mt0, 2));
        mt1 = fmaxf(mt1, __shfl_xor_sync(0xffffffff, mt1, 1));
        mt1 = fmaxf(mt1, __shfl_xor_sync(0xffffffff, mt1, 2));

        float mn0 = fmaxf(m0r, mt0), mn1 = fmaxf(m1r, mt1);
        float a0 = __expf(m0r - mn0), a1 = __expf(m1r - mn1);
        m0r = mn0; m1r = mn1;

        float lt0 = 0.0f, lt1 = 0.0f;
#pragma unroll
        for (int nt = 0; nt < 8; nt++) {
            s4[nt][0] = __expf(s4[nt][0] - mn0);
            s4[nt][1] = __expf(s4[nt][1] - mn0);
            s4[nt][2] = __expf(s4[nt][2] - mn1);
            s4[nt][3] = __expf(s4[nt][3] - mn1);
            lt0 += s4[nt][0] + s4[nt][1];
            lt1 += s4[nt][2] + s4[nt][3];
        }
        lt0 += __shfl_xor_sync(0xffffffff, lt0, 1);
        lt0 += __shfl_xor_sync(0xffffffff, lt0, 2);
        lt1 += __shfl_xor_sync(0xffffffff, lt1, 1);
        lt1 += __shfl_xor_sync(0xffffffff, lt1, 2);
        l0r = l0r * a0 + lt0;
        l1r = l1r * a1 + lt1;

#pragma unroll
        for (int nt = 0; nt < 8; nt++) {
            o[nt][0] *= a0; o[nt][1] *= a0;
            o[nt][2] *= a1; o[nt][3] *= a1;
        }

        // ---- O += P @ V  (P in regs, permuted keys; V^T LDS64 b-frags) ----
#pragma unroll
        for (int kb = 0; kb < 8; kb++) {
            uint32_t pa0 = to_tf32(s4[kb][0]);
            uint32_t pa1 = to_tf32(s4[kb][2]);
            uint32_t pa2 = to_tf32(s4[kb][1]);
            uint32_t pa3 = to_tf32(s4[kb][3]);
            const int koff = kb * 8 + 2 * tq;
#pragma unroll
            for (int nt = 0; nt < 8; nt++) {
                uint2 vv = *reinterpret_cast<const uint2*>(
                    &Vt_s[(nt * 8 + g) * 72 + koff]);
                mma_tf32(o[nt], pa0, pa1, pa2, pa3, vv.x, vv.y);
            }
        }
        __syncthreads();
    }

    const float inv0 = 1.0f / l0r, inv1 = 1.0f / l1r;
    const size_t row0 = rbase + q0 + wq + g;
    const size_t row1 = row0 + 8;
#pragma unroll
    for (int nt = 0; nt < 8; nt++) {
        const int col = hoff + nt * 8 + 2 * tq;
        *reinterpret_cast<uint2*>(&atttf[row0 * EMB + col]) =
            make_uint2(to_tf32(o[nt][0] * inv0), to_tf32(o[nt][1] * inv0));
        *reinterpret_cast<uint2*>(&atttf[row1 * EMB + col]) =
            make_uint2(to_tf32(o[nt][2] * inv1), to_tf32(o[nt][3] * inv1));
    }
}

// ============================================================================
extern "C" void kernel_launch(void* const* d_in, const int* in_sizes, int n_in,
                              void* d_out, int out_size) {
    const float* x      = (const float*)d_in[0];
    const void*  mask   = d_in[1];
    const float* W_pre  = (const float*)d_in[2];
    const float* b_pre  = (const float*)d_in[3];
    const float* W_proj = (const float*)d_in[4];
    const float* b_proj = (const float*)d_in[5];
    float* out = (float*)d_out;

    uint32_t *qtf, *ktf, *vtf, *xtf, *atttf, *wpretf, *wprojtf;
    cudaGetSymbolAddress((void**)&qtf, g_qtf);
    cudaGetSymbolAddress((void**)&ktf, g_ktf);
    cudaGetSymbolAddress((void**)&vtf, g_vtf);
    cudaGetSymbolAddress((void**)&xtf, g_xtf);
    cudaGetSymbolAddress((void**)&atttf, g_atttf);
    cudaGetSymbolAddress((void**)&wpretf, g_wpretf);
    cudaGetSymbolAddress((void**)&wprojtf, g_wprojtf);

    mask_scan_kernel<<<512, 256>>>((const uint4*)mask);
    cvt_all_kernel<<<2048, 256>>>((const float4*)x, (const float4*)W_pre,
                                  (const float4*)W_proj,
                                  (uint4*)xtf, (uint4*)wpretf, (uint4*)wprojtf);

    cudaFuncSetAttribute(gemm_tf_kernel<0>,
                         cudaFuncAttributeMaxDynamicSharedMemorySize, G5_BYTES);
    cudaFuncSetAttribute(gemm_tf_kernel<1>,
                         cudaFuncAttributeMaxDynamicSharedMemorySize, G5_BYTES);
    cudaFuncSetAttribute(attn_mma_kernel,
                         cudaFuncAttributeMaxDynamicSharedMemorySize, AT4_BYTES);

    // 1) QKV GEMM -> attention-ready operands (Q/K permuted, V transposed)
    {
        dim3 grid(QKVN / 128, ROWS / 128);
        gemm_tf_kernel<1><<<grid, 256, G5_BYTES>>>(
            xtf, wpretf, b_pre, nullptr, qtf, ktf, vtf, ROWS, QKVN, EMB);
    }
    // 2) Attention (LDS64 fragment loads)
    {
        dim3 grid(SEQ / 128, HEADS, BATCH);
        attn_mma_kernel<<<grid, 256, AT4_BYTES>>>(qtf, ktf, vtf, mask, atttf);
    }
    // 3) Projection GEMM
    {
        dim3 grid(EMB / 128, ROWS / 128);
        gemm_tf_kernel<0><<<grid, 256, G5_BYTES>>>(
            atttf, wprojtf, b_proj, out, nullptr, nullptr, nullptr,
            ROWS, EMB, EMB);
    }
}

// round 17
// speedup vs baseline: 1.0062x; 1.0062x over previous
#include <cuda_runtime.h>
#include <math.h>
#include <stdint.h>

#define HEADS 12
#define DIM   64
#define BATCH 2
#define SEQ   2048
#define EMB   768
#define QKVN  (3 * HEADS * DIM)   // 2304
#define ROWS  (BATCH * SEQ)       // 4096
#define MASKN (BATCH * SEQ * SEQ) // 8388608

// ----- device scratch -----
__device__ uint32_t g_qtf[ROWS * EMB];
__device__ uint32_t g_ktf[ROWS * EMB];
__device__ uint32_t g_vtf[ROWS * EMB];
__device__ uint32_t g_xtf[ROWS * EMB];
__device__ uint32_t g_atttf[ROWS * EMB];
__device__ uint32_t g_wpretf[EMB * QKVN];
__device__ uint32_t g_wprojtf[EMB * EMB];
__device__ float g_opart[2 * ROWS * EMB];          // unnormalized O partials
__device__ float g_ml[2 * ROWS * HEADS * 2];       // per (half,row,head): m,l
__device__ int   g_mask_esize;
__device__ int   g_mask_allones;

// ============================ helpers =======================================
__device__ __forceinline__ uint32_t to_tf32(float x) {
    uint32_t r;
    asm("cvt.rna.tf32.f32 %0, %1;" : "=r"(r) : "f"(x));
    return r;
}
__device__ __forceinline__ void mma_tf32(float c[4],
                                         uint32_t a0, uint32_t a1, uint32_t a2, uint32_t a3,
                                         uint32_t b0, uint32_t b1) {
    asm volatile(
        "mma.sync.aligned.m16n8k8.row.col.f32.tf32.tf32.f32 "
        "{%0,%1,%2,%3}, {%4,%5,%6,%7}, {%8,%9}, {%0,%1,%2,%3};"
        : "+f"(c[0]), "+f"(c[1]), "+f"(c[2]), "+f"(c[3])
        : "r"(a0), "r"(a1), "r"(a2), "r"(a3), "r"(b0), "r"(b1));
}
#define CP16(dst, src) \
    asm volatile("cp.async.cg.shared.global [%0], [%1], 16;" :: "r"(dst), "l"(src) : "memory")
#define CP_COMMIT() asm volatile("cp.async.commit_group;" ::: "memory")
#define CP_WAIT1() asm volatile("cp.async.wait_group 1;" ::: "memory")
#define CP_WAIT0() asm volatile("cp.async.wait_group 0;" ::: "memory")

// ============================ fused prepass: fp32 -> tf32 ===================
#define XN4  (ROWS * EMB / 4)
#define WPN4 (EMB * QKVN / 4)
#define WJN4 (EMB * EMB / 4)
#define TOTN4 (XN4 + WPN4 + WJN4)

__global__ void cvt_all_kernel(const float4* __restrict__ x,
                               const float4* __restrict__ wpre,
                               const float4* __restrict__ wproj,
                               uint4* __restrict__ xo,
                               uint4* __restrict__ wpo,
                               uint4* __restrict__ wjo) {
    for (int i = blockIdx.x * blockDim.x + threadIdx.x; i < TOTN4;
         i += gridDim.x * blockDim.x) {
        const float4* src;
        uint4* dst;
        int k;
        if (i < XN4) { src = x; dst = xo; k = i; }
        else if (i < XN4 + WPN4) { src = wpre; dst = wpo; k = i - XN4; }
        else { src = wproj; dst = wjo; k = i - XN4 - WPN4; }
        float4 v = src[k];
        dst[k] = make_uint4(to_tf32(v.x), to_tf32(v.y), to_tf32(v.z), to_tf32(v.w));
    }
}

// ============================ GEMM 128x128 tile (single tf32) ===============
#define G5_BYTES 71680

template <int MODE>
__global__ void __launch_bounds__(256, 2)
gemm_tf_kernel(const uint32_t* __restrict__ Atf, const uint32_t* __restrict__ Btf,
               const float* __restrict__ bias, float* __restrict__ C,
               uint32_t* __restrict__ qtf, uint32_t* __restrict__ ktf,
               uint32_t* __restrict__ vtf,
               int M, int N, int K) {
    extern __shared__ char smraw[];
    uint32_t* usm = reinterpret_cast<uint32_t*>(smraw);
    const uint32_t sb = (uint32_t)__cvta_generic_to_shared(smraw);

    const int tid = threadIdx.x;
    const int wid = tid >> 5;
    const int lane = tid & 31;
    const int g  = lane >> 2;
    const int tq = lane & 3;
    const int wm = wid >> 1;
    const int wn = wid & 1;
    const int m0 = blockIdx.y * 128;
    const int n0 = blockIdx.x * 128;
    const int nkt = K / 32;

    float acc[2][8][4];
#pragma unroll
    for (int i = 0; i < 2; i++)
#pragma unroll
        for (int j = 0; j < 8; j++)
#pragma unroll
            for (int r = 0; r < 4; r++) acc[i][j][r] = 0.0f;

    auto issue_tile = [&](int s, int kt) {
#pragma unroll
        for (int p = 0; p < 4; p++) {
            int idx = p * 256 + tid;
            int r = idx >> 3, ch = idx & 7;
            const uint32_t* src = Atf + (size_t)(m0 + r) * K + kt * 32 + ch * 4;
            uint32_t dst = sb + s * 18432 + (r * 36 + ch * 4) * 4;
            CP16(dst, src);
        }
#pragma unroll
        for (int p = 0; p < 4; p++) {
            int idx = p * 256 + tid;
            int r = idx >> 5, ch = idx & 31;
            const uint32_t* src = Btf + (size_t)(kt * 32 + r) * N + n0 + ch * 4;
            uint32_t dst = sb + 36864 + s * 17408 + (r * 136 + ch * 4) * 4;
            CP16(dst, src);
        }
        CP_COMMIT();
    };

    issue_tile(0, 0);

    for (int kt = 0; kt < nkt; kt++) {
        const int s = kt & 1;
        if (kt + 1 < nkt) {
            issue_tile(1 - s, kt + 1);
            CP_WAIT1();
        } else {
            CP_WAIT0();
        }
        __syncthreads();

        const uint32_t* sA = usm + s * 4608;
        const uint32_t* sB = usm + 9216 + s * 4352;

#pragma unroll
        for (int ks = 0; ks < 4; ks++) {
            const int kb = ks * 8;
            uint32_t af[2][4];
#pragma unroll
            for (int i = 0; i < 2; i++) {
                const int rbase = (wm * 32 + i * 16 + g) * 36 + kb + tq;
                af[i][0] = sA[rbase];
                af[i][1] = sA[rbase + 8 * 36];
                af[i][2] = sA[rbase + 4];
                af[i][3] = sA[rbase + 8 * 36 + 4];
            }
            uint32_t bf[8][2];
#pragma unroll
            for (int j = 0; j < 8; j++) {
                const int col = wn * 64 + j * 8 + g;
                bf[j][0] = sB[(kb + tq) * 136 + col];
                bf[j][1] = sB[(kb + tq + 4) * 136 + col];
            }
#pragma unroll
            for (int i = 0; i < 2; i++)
#pragma unroll
                for (int j = 0; j < 8; j++)
                    mma_tf32(acc[i][j], af[i][0], af[i][1], af[i][2], af[i][3],
                             bf[j][0], bf[j][1]);
        }
        __syncthreads();
    }

    const int region = n0 / EMB;
#pragma unroll
    for (int i = 0; i < 2; i++) {
        const int row = m0 + wm * 32 + i * 16 + g;
#pragma unroll
        for (int j = 0; j < 8; j++) {
            const int col = n0 + wn * 64 + j * 8 + 2 * tq;
            const float b0 = bias[col], b1 = bias[col + 1];
            float v00 = acc[i][j][0] + b0, v01 = acc[i][j][1] + b1;
            float v10 = acc[i][j][2] + b0, v11 = acc[i][j][3] + b1;
            if (MODE == 0) {
                *reinterpret_cast<float2*>(&C[(size_t)row * N + col]) =
                    make_float2(v00, v01);
                *reinterpret_cast<float2*>(&C[(size_t)(row + 8) * N + col]) =
                    make_float2(v10, v11);
            } else {
                const int cemb = col - region * EMB;
                const size_t a0 = (size_t)row * EMB + cemb;
                const size_t a1 = (size_t)(row + 8) * EMB + cemb;
                uint32_t* dst = (region == 0) ? qtf : (region == 1) ? ktf : vtf;
                const float sc = (region == 0) ? 0.125f : 1.0f;
                *reinterpret_cast<uint2*>(&dst[a0]) =
                    make_uint2(to_tf32(sc * v00), to_tf32(sc * v01));
                *reinterpret_cast<uint2*>(&dst[a1]) =
                    make_uint2(to_tf32(sc * v10), to_tf32(sc * v11));
            }
        }
    }
}

// ============================ mask scan (detect fused) ======================
__device__ __forceinline__ unsigned int haszero_byte(unsigned int v) {
    return (v - 0x01010101u) & ~v & 0x80808080u;
}

__global__ void mask_scan_kernel(const uint4* __restrict__ mask) {
    unsigned int w0 = ((const unsigned int*)mask)[0];
    int esize;
    if (w0 == 0x01010101u) esize = 1;
    else if (w0 == 1u || w0 == 0x3f800000u) esize = 4;
    else if ((w0 & 0xFFu) != 0u || (w0 >> 8) == 0u) esize = 1;
    else esize = 4;
    if (blockIdx.x == 0 && threadIdx.x == 0) {
        g_mask_esize = esize;
        g_mask_allones = 1;
    }
    unsigned int any = 0;
    if (esize == 4) {
        const int n = MASKN / 4;
        for (int i = blockIdx.x * blockDim.x + threadIdx.x; i < n;
             i += gridDim.x * blockDim.x) {
            uint4 w = mask[i];
            any |= (w.x == 0u) | (w.y == 0u) | (w.z == 0u) | (w.w == 0u);
        }
    } else {
        const int n = MASKN / 16;
        for (int i = blockIdx.x * blockDim.x + threadIdx.x; i < n;
             i += gridDim.x * blockDim.x) {
            uint4 w = mask[i];
            any |= haszero_byte(w.x) | haszero_byte(w.y) |
                   haszero_byte(w.z) | haszero_byte(w.w);
        }
    }
    if (any) g_mask_allones = 0;
}

// ============================ attention: cross-CTA split-K(2) ===============
// R14-winner inner loop; each CTA handles HALF the key range (16 chunks).
// grid = (SEQ/128, HEADS, BATCH*2), z = half*BATCH + b.
// Outputs UNNORMALIZED O (fp32) to g_opart[half] and (m,l) to g_ml[half].
#define AT4_BYTES (18432 * 4)

__global__ void __launch_bounds__(256, 2)
attn_mma_kernel(const uint32_t* __restrict__ qtf, const uint32_t* __restrict__ ktf,
                const uint32_t* __restrict__ vtf,
                const void* __restrict__ mask,
                float* __restrict__ opart, float* __restrict__ ml) {
    extern __shared__ float sh[];
    const uint32_t sb = (uint32_t)__cvta_generic_to_shared(sh);

    const int tid = threadIdx.x;
    const int wid = tid >> 5;
    const int lane = tid & 31;
    const int g  = lane >> 2;
    const int tq = lane & 3;
    const int wq = wid * 16;
    const int q0 = blockIdx.x * 128;
    const int h  = blockIdx.y;
    const int half = blockIdx.z >> 1;
    const int b  = blockIdx.z & 1;

    const int mask_allones = g_mask_allones;
    const int mask_esize   = g_mask_esize;
    const size_t rbase = (size_t)b * SEQ;
    const int hoff = h * DIM;
    const size_t mask_base = (size_t)b * SEQ * SEQ;

    auto issue_kv = [&](int s, int kt) {
        const int k0 = kt * 64;
#pragma unroll
        for (int p = 0; p < 4; p++) {
            int idx = p * 256 + tid;
            int key = idx >> 4, c = idx & 15;
            const uint32_t* src = ktf + (rbase + k0 + key) * EMB + hoff + c * 4;
            uint32_t dst = sb + (s * 9216 + key * 68 + c * 4) * 4;
            CP16(dst, src);
        }
#pragma unroll
        for (int p = 0; p < 4; p++) {
            int idx = p * 256 + tid;
            int key = idx >> 4, c = idx & 15;
            const uint32_t* src = vtf + (rbase + k0 + key) * EMB + hoff + c * 4;
            uint32_t dst = sb + (s * 9216 + 4352 + key * 76 + c * 4) * 4;
            CP16(dst, src);
        }
        CP_COMMIT();
    };

#pragma unroll
    for (int p = 0; p < 8; p++) {
        int idx = p * 256 + tid;
        int r = idx >> 4, c = idx & 15;
        const uint32_t* src = qtf + (rbase + q0 + r) * EMB + hoff + c * 4;
        uint32_t dst = sb + (9216 + r * 68 + c * 4) * 4;
        CP16(dst, src);
    }
    CP_COMMIT();
    CP_WAIT0();
    __syncthreads();

    const uint32_t* Qstage = reinterpret_cast<const uint32_t*>(sh + 9216);
    uint32_t qf[8][4];
#pragma unroll
    for (int kb = 0; kb < 8; kb++) {
        const int r0 = (wq + g) * 68 + kb * 8 + tq;
        const int r1 = (wq + g + 8) * 68 + kb * 8 + tq;
        qf[kb][0] = Qstage[r0];
        qf[kb][1] = Qstage[r1];
        qf[kb][2] = Qstage[r0 + 4];
        qf[kb][3] = Qstage[r1 + 4];
    }
    __syncthreads();

    const int kt_beg = half * (SEQ / 128);   // 16 chunks per half
    const int kt_end = kt_beg + (SEQ / 128);
    issue_kv(0, kt_beg);

    float o[8][4];
#pragma unroll
    for (int nt = 0; nt < 8; nt++)
#pragma unroll
        for (int r = 0; r < 4; r++) o[nt][r] = 0.0f;
    float m0r = -1e30f, m1r = -1e30f, l0r = 0.0f, l1r = 0.0f;

    for (int kt = kt_beg; kt < kt_end; kt++) {
        const int s = kt & 1;
        const int k0 = kt * 64;
        if (kt + 1 < kt_end) {
            issue_kv(1 - s, kt + 1);
            CP_WAIT1();
        } else {
            CP_WAIT0();
        }
        __syncthreads();

        const uint32_t* Ktf_s = reinterpret_cast<const uint32_t*>(sh + s * 9216);
        const uint32_t* Vtf_s = reinterpret_cast<const uint32_t*>(sh + s * 9216 + 4352);

        float s4[8][4];
#pragma unroll
        for (int nt = 0; nt < 8; nt++)
#pragma unroll
            for (int r = 0; r < 4; r++) s4[nt][r] = 0.0f;
#pragma unroll
        for (int kb = 0; kb < 8; kb++) {
#pragma unroll
            for (int nt = 0; nt < 8; nt++) {
                uint32_t b0 = Ktf_s[(nt * 8 + g) * 68 + kb * 8 + tq];
                uint32_t b1 = Ktf_s[(nt * 8 + g) * 68 + kb * 8 + tq + 4];
                mma_tf32(s4[nt], qf[kb][0], qf[kb][1], qf[kb][2], qf[kb][3], b0, b1);
            }
        }

        if (!mask_allones) {
            const int qg0 = q0 + wq + g, qg1 = qg0 + 8;
#pragma unroll
            for (int nt = 0; nt < 8; nt++) {
                int kcol = k0 + nt * 8 + 2 * tq;
                bool mk[4];
                if (mask_esize == 4) {
                    const unsigned int* mm = (const unsigned int*)mask;
                    mk[0] = mm[mask_base + (size_t)qg0 * SEQ + kcol] != 0;
                    mk[1] = mm[mask_base + (size_t)qg0 * SEQ + kcol + 1] != 0;
                    mk[2] = mm[mask_base + (size_t)qg1 * SEQ + kcol] != 0;
                    mk[3] = mm[mask_base + (size_t)qg1 * SEQ + kcol + 1] != 0;
                } else {
                    const unsigned char* mm = (const unsigned char*)mask;
                    mk[0] = mm[mask_base + (size_t)qg0 * SEQ + kcol] != 0;
                    mk[1] = mm[mask_base + (size_t)qg0 * SEQ + kcol + 1] != 0;
                    mk[2] = mm[mask_base + (size_t)qg1 * SEQ + kcol] != 0;
                    mk[3] = mm[mask_base + (size_t)qg1 * SEQ + kcol + 1] != 0;
                }
#pragma unroll
                for (int r = 0; r < 4; r++)
                    if (!mk[r]) s4[nt][r] = -1e9f;
            }
        }

        float mt0 = -1e30f, mt1 = -1e30f;
#pragma unroll
        for (int nt = 0; nt < 8; nt++) {
            mt0 = fmaxf(mt0, fmaxf(s4[nt][0], s4[nt][1]));
            mt1 = fmaxf(mt1, fmaxf(s4[nt][2], s4[nt][3]));
        }
        mt0 = fmaxf(mt0, __shfl_xor_sync(0xffffffff, mt0, 1));
        mt0 = fmaxf(mt0, __shfl_xor_sync(0xffffffff, mt0, 2));
        mt1 = fmaxf(mt1, __shfl_xor_sync(0xffffffff, mt1, 1));
        mt1 = fmaxf(mt1, __shfl_xor_sync(0xffffffff, mt1, 2));

        float mn0 = fmaxf(m0r, mt0), mn1 = fmaxf(m1r, mt1);
        float a0 = __expf(m0r - mn0), a1 = __expf(m1r - mn1);
        m0r = mn0; m1r = mn1;

        float lt0 = 0.0f, lt1 = 0.0f;
#pragma unroll
        for (int nt = 0; nt < 8; nt++) {
            s4[nt][0] = __expf(s4[nt][0] - mn0);
            s4[nt][1] = __expf(s4[nt][1] - mn0);
            s4[nt][2] = __expf(s4[nt][2] - mn1);
            s4[nt][3] = __expf(s4[nt][3] - mn1);
            lt0 += s4[nt][0] + s4[nt][1];
            lt1 += s4[nt][2] + s4[nt][3];
        }
        lt0 += __shfl_xor_sync(0xffffffff, lt0, 1);
        lt0 += __shfl_xor_sync(0xffffffff, lt0, 2);
        lt1 += __shfl_xor_sync(0xffffffff, lt1, 1);
        lt1 += __shfl_xor_sync(0xffffffff, lt1, 2);
        l0r = l0r * a0 + lt0;
        l1r = l1r * a1 + lt1;

#pragma unroll
        for (int nt = 0; nt < 8; nt++) {
            o[nt][0] *= a0; o[nt][1] *= a0;
            o[nt][2] *= a1; o[nt][3] *= a1;
        }

#pragma unroll
        for (int kb = 0; kb < 8; kb++) {
            uint32_t pa0 = to_tf32(s4[kb][0]);
            uint32_t pa1 = to_tf32(s4[kb][2]);
            uint32_t pa2 = to_tf32(s4[kb][1]);
            uint32_t pa3 = to_tf32(s4[kb][3]);
            const int vr0 = (kb * 8 + 2 * tq) * 76;
            const int vr1 = (kb * 8 + 2 * tq + 1) * 76;
#pragma unroll
            for (int nt = 0; nt < 8; nt++) {
                const int d = nt * 8 + g;
                mma_tf32(o[nt], pa0, pa1, pa2, pa3,
                         Vtf_s[vr0 + d], Vtf_s[vr1 + d]);
            }
        }
        __syncthreads();
    }

    // ---- write UNNORMALIZED partials + (m,l) ----
    const size_t prow0 = (size_t)half * ROWS + rbase + q0 + wq + g;
    const size_t prow1 = prow0 + 8;
#pragma unroll
    for (int nt = 0; nt < 8; nt++) {
        const int col = hoff + nt * 8 + 2 * tq;
        *reinterpret_cast<float2*>(&opart[prow0 * EMB + col]) =
            make_float2(o[nt][0], o[nt][1]);
        *reinterpret_cast<float2*>(&opart[prow1 * EMB + col]) =
            make_float2(o[nt][2], o[nt][3]);
    }
    if (tq == 0) {
        ml[(prow0 * HEADS + h) * 2 + 0] = m0r;
        ml[(prow0 * HEADS + h) * 2 + 1] = l0r;
        ml[(prow1 * HEADS + h) * 2 + 0] = m1r;
        ml[(prow1 * HEADS + h) * 2 + 1] = l1r;
    }
}

// ============================ split-K combine (exact flash merge) ===========
__global__ void combine_kernel(const float2* __restrict__ opart,
                               const float* __restrict__ ml,
                               uint32_t* __restrict__ atttf) {
    const int n2 = ROWS * EMB / 2;
    for (int i = blockIdx.x * blockDim.x + threadIdx.x; i < n2;
         i += gridDim.x * blockDim.x) {
        const int e = i * 2;
        const int row = e / EMB;
        const int col = e - row * EMB;
        const int h = col >> 6;
        const float m0 = ml[((size_t)row * HEADS + h) * 2 + 0];
        const float l0 = ml[((size_t)row * HEADS + h) * 2 + 1];
        const float m1 = ml[(((size_t)ROWS + row) * HEADS + h) * 2 + 0];
        const float l1 = ml[(((size_t)ROWS + row) * HEADS + h) * 2 + 1];
        const float M = fmaxf(m0, m1);
        const float e0 = __expf(m0 - M), e1 = __expf(m1 - M);
        const float inv = 1.0f / (e0 * l0 + e1 * l1);
        float2 p0 = opart[i];
        float2 p1 = opart[(size_t)(ROWS * EMB / 2) + i];
        *reinterpret_cast<uint2*>(&atttf[e]) =
            make_uint2(to_tf32((e0 * p0.x + e1 * p1.x) * inv),
                       to_tf32((e0 * p0.y + e1 * p1.y) * inv));
    }
}

// ============================================================================
extern "C" void kernel_launch(void* const* d_in, const int* in_sizes, int n_in,
                              void* d_out, int out_size) {
    const float* x      = (const float*)d_in[0];
    const void*  mask   = d_in[1];
    const float* W_pre  = (const float*)d_in[2];
    const float* b_pre  = (const float*)d_in[3];
    const float* W_proj = (const float*)d_in[4];
    const float* b_proj = (const float*)d_in[5];
    float* out = (float*)d_out;

    uint32_t *qtf, *ktf, *vtf, *xtf, *atttf, *wpretf, *wprojtf;
    float *opart, *ml;
    cudaGetSymbolAddress((void**)&qtf, g_qtf);
    cudaGetSymbolAddress((void**)&ktf, g_ktf);
    cudaGetSymbolAddress((void**)&vtf, g_vtf);
    cudaGetSymbolAddress((void**)&xtf, g_xtf);
    cudaGetSymbolAddress((void**)&atttf, g_atttf);
    cudaGetSymbolAddress((void**)&wpretf, g_wpretf);
    cudaGetSymbolAddress((void**)&wprojtf, g_wprojtf);
    cudaGetSymbolAddress((void**)&opart, g_opart);
    cudaGetSymbolAddress((void**)&ml, g_ml);

    mask_scan_kernel<<<512, 256>>>((const uint4*)mask);
    cvt_all_kernel<<<2048, 256>>>((const float4*)x, (const float4*)W_pre,
                                  (const float4*)W_proj,
                                  (uint4*)xtf, (uint4*)wpretf, (uint4*)wprojtf);

    cudaFuncSetAttribute(gemm_tf_kernel<0>,
                         cudaFuncAttributeMaxDynamicSharedMemorySize, G5_BYTES);
    cudaFuncSetAttribute(gemm_tf_kernel<1>,
                         cudaFuncAttributeMaxDynamicSharedMemorySize, G5_BYTES);
    cudaFuncSetAttribute(attn_mma_kernel,
                         cudaFuncAttributeMaxDynamicSharedMemorySize, AT4_BYTES);

    // 1) QKV GEMM -> attention-ready operands
    {
        dim3 grid(QKVN / 128, ROWS / 128);
        gemm_tf_kernel<1><<<grid, 256, G5_BYTES>>>(
            xtf, wpretf, b_pre, nullptr, qtf, ktf, vtf, ROWS, QKVN, EMB);
    }
    // 2) Attention split-K(2): 768 CTAs of half work
    {
        dim3 grid(SEQ / 128, HEADS, BATCH * 2);
        attn_mma_kernel<<<grid, 256, AT4_BYTES>>>(qtf, ktf, vtf, mask,
                                                  opart, ml);
    }
    // 2b) Exact merge of the two key-halves
    combine_kernel<<<1536, 256>>>((const float2*)opart, ml, atttf);

    // 3) Projection GEMM
    {
        dim3 grid(EMB / 128, ROWS / 128);
        gemm_tf_kernel<0><<<grid, 256, G5_BYTES>>>(
            atttf, wprojtf, b_proj, out, nullptr, nullptr, nullptr,
            ROWS, EMB, EMB);
    }
}